// round 11
// baseline (speedup 1.0000x reference)
#include <cuda_runtime.h>
#include <cstdint>

// Problem constants (fixed shapes)
#define NN 50000
#define EE 800000
#define DD 256
#define KK 256
#define NCLS 40
#define STATS_BLOCKS 400
#define BN_EPS 1e-5f

// ---------------- scratch (static device globals; no allocation) ----------------
__device__ __align__(16) float g_Gs[NN * DD];     // GEMM self output [N,256]
__device__ __align__(16) float g_Gn[NN * DD];     // GEMM neigh output [N,256]
__device__ __align__(16) float g_Z[NN * DD];      // pre-BN activations
__device__ __align__(16) uint32_t g_Ahi[NN * 128];   // A hi-plane (bf16x2 words)
__device__ __align__(16) uint32_t g_Alo[NN * 128];   // A lo-plane
__device__ __align__(16) uint32_t g_Whi[512 * 128];  // W0 hi-plane [self;neigh]
__device__ __align__(16) uint32_t g_Wlo[512 * 128];  // W0 lo-plane
__device__ __align__(16) uint32_t g_W1hi[512 * 128]; // W1 planes
__device__ __align__(16) uint32_t g_W1lo[512 * 128];
__device__ __align__(16) uint32_t g_W2hi[128 * 128]; // W2 planes (40 self + 40 neigh + pad)
__device__ __align__(16) uint32_t g_W2lo[128 * 128];
__device__ float g_part[STATS_BLOCKS * 512];
__device__ float g_affine[1024];  // [0:256)=A_z,[256:512)=B_z,[512:768)=A_plm,[768:1024)=B_plm
__device__ float g_invdeg[NN];
__device__ __align__(16) int g_deg[NN];
__device__ __align__(16) int g_fill[NN];
__device__ int g_rowptr[NN + 1];
__device__ int g_csr[EE];

// ---------------- bf16 hi/lo split helpers ----------------
__device__ __forceinline__ uint32_t pack_bf16x2(float lo_elem, float hi_elem) {
    uint32_t r;
    asm("cvt.rn.bf16x2.f32 %0, %1, %2;" : "=r"(r) : "f"(hi_elem), "f"(lo_elem));
    return r;
}

__device__ __forceinline__ void split_pair(float v0, float v1, uint32_t& hi, uint32_t& lo) {
    uint32_t h = pack_bf16x2(v0, v1);
    float h0 = __uint_as_float(h << 16);
    float h1 = __uint_as_float(h & 0xffff0000u);
    lo = pack_bf16x2(v0 - h0, v1 - h1);
    hi = h;
}

__device__ __forceinline__ void split4(float4 v, uint2& h, uint2& l) {
    uint32_t h0, l0, h1, l1;
    split_pair(v.x, v.y, h0, l0);
    split_pair(v.z, v.w, h1, l1);
    h = make_uint2(h0, h1);
    l = make_uint2(l0, l1);
}

__device__ __forceinline__ void mma_bf16(float* d, const uint32_t* a, const uint32_t* b) {
    asm volatile(
        "mma.sync.aligned.m16n8k16.row.col.f32.bf16.bf16.f32 "
        "{%0,%1,%2,%3}, {%4,%5,%6,%7}, {%8,%9}, {%0,%1,%2,%3};"
        : "+f"(d[0]), "+f"(d[1]), "+f"(d[2]), "+f"(d[3])
        : "r"(a[0]), "r"(a[1]), "r"(a[2]), "r"(a[3]), "r"(b[0]), "r"(b[1]));
}

__device__ __forceinline__ void ldsm4(uint32_t* r, uint32_t addr) {
    asm volatile("ldmatrix.sync.aligned.m8n8.x4.shared.b16 {%0,%1,%2,%3}, [%4];"
                 : "=r"(r[0]), "=r"(r[1]), "=r"(r[2]), "=r"(r[3])
                 : "r"(addr));
}

__device__ __forceinline__ uint32_t smem_u32(const void* p) {
    uint32_t a;
    asm("{ .reg .u64 t; cvta.to.shared.u64 t, %1; cvt.u32.u64 %0, t; }" : "=r"(a) : "l"(p));
    return a;
}

__device__ __forceinline__ void cp_async16(uint32_t dst, const void* src, uint32_t sz) {
    asm volatile("cp.async.cg.shared.global [%0], [%1], 16, %2;"
                 :: "r"(dst), "l"(src), "r"(sz) : "memory");
}
__device__ __forceinline__ void cp_commit() {
    asm volatile("cp.async.commit_group;" ::: "memory");
}
__device__ __forceinline__ void cp_wait0() {
    asm volatile("cp.async.wait_group 0;" ::: "memory");
}

// ---------------- split kernels ----------------
__global__ void k_split_w(const float* __restrict__ Bs, const float* __restrict__ Bn,
                          uint32_t* __restrict__ Whi, uint32_t* __restrict__ Wlo) {
    int q = blockIdx.x * blockDim.x + threadIdx.x;  // float4 idx, 512*64
    int row = q >> 6, wq = q & 63;
    const float* src = (row < 256) ? (Bs + row * KK) : (Bn + (row - 256) * KK);
    float4 v = *reinterpret_cast<const float4*>(src + wq * 4);
    uint2 h, l;
    split4(v, h, l);
    *reinterpret_cast<uint2*>(Whi + row * 128 + wq * 2) = h;
    *reinterpret_cast<uint2*>(Wlo + row * 128 + wq * 2) = l;
}

// layer-2 weights: rows 0-39 = ws2, 40-79 = wn2, 80-127 = zero pad
__global__ void k_split_w2(const float* __restrict__ Bs, const float* __restrict__ Bn,
                           uint32_t* __restrict__ Whi, uint32_t* __restrict__ Wlo) {
    int q = blockIdx.x * blockDim.x + threadIdx.x;  // float4 idx, 128*64 = 8192
    int row = q >> 6, wq = q & 63;
    float4 v = make_float4(0.f, 0.f, 0.f, 0.f);
    if (row < NCLS) v = *reinterpret_cast<const float4*>(Bs + row * KK + wq * 4);
    else if (row < 2 * NCLS) v = *reinterpret_cast<const float4*>(Bn + (row - NCLS) * KK + wq * 4);
    uint2 h, l;
    split4(v, h, l);
    *reinterpret_cast<uint2*>(Whi + row * 128 + wq * 2) = h;
    *reinterpret_cast<uint2*>(Wlo + row * 128 + wq * 2) = l;
}

// Activations: MODE 0 = raw; MODE 1 = relu(Az*A+Bz + Ap*P+Bp); MODE 2 = relu(Az*A+Bz)
template <int MODE>
__global__ void k_split_a(const float* __restrict__ A, const float* __restrict__ P,
                          const float* __restrict__ aff,
                          uint32_t* __restrict__ Ahi, uint32_t* __restrict__ Alo) {
    int q = blockIdx.x * blockDim.x + threadIdx.x;  // float4 idx, NN*64 exact
    float4 a = reinterpret_cast<const float4*>(A)[q];
    if (MODE != 0) {
        int cb = (q & 63) << 2;
        float4 az = *reinterpret_cast<const float4*>(aff + cb);
        float4 bz = *reinterpret_cast<const float4*>(aff + 256 + cb);
        a.x = fmaf(az.x, a.x, bz.x);
        a.y = fmaf(az.y, a.y, bz.y);
        a.z = fmaf(az.z, a.z, bz.z);
        a.w = fmaf(az.w, a.w, bz.w);
        if (MODE == 1) {
            float4 ap = *reinterpret_cast<const float4*>(aff + 512 + cb);
            float4 bp = *reinterpret_cast<const float4*>(aff + 768 + cb);
            float4 p = reinterpret_cast<const float4*>(P)[q];
            a.x += fmaf(ap.x, p.x, bp.x);
            a.y += fmaf(ap.y, p.y, bp.y);
            a.z += fmaf(ap.z, p.z, bp.z);
            a.w += fmaf(ap.w, p.w, bp.w);
        }
        a.x = fmaxf(a.x, 0.f); a.y = fmaxf(a.y, 0.f);
        a.z = fmaxf(a.z, 0.f); a.w = fmaxf(a.w, 0.f);
    }
    uint2 h, l;
    split4(a, h, l);
    reinterpret_cast<uint2*>(Ahi)[q] = h;
    reinterpret_cast<uint2*>(Alo)[q] = l;
}

// ---------------- zero deg/fill ----------------
__global__ void k_zero() {
    int q = blockIdx.x * blockDim.x + threadIdx.x;
    if (q < NN / 4) {
        int4 z = make_int4(0, 0, 0, 0);
        reinterpret_cast<int4*>(g_deg)[q] = z;
        reinterpret_cast<int4*>(g_fill)[q] = z;
    }
}

// ---------------- CSR build ----------------
__global__ void k_hist(const int* __restrict__ dst) {
    int e = blockIdx.x * blockDim.x + threadIdx.x;
    if (e < EE) atomicAdd(&g_deg[dst[e]], 1);
}

__global__ void k_scan() {
    const int n = NN;
    const int CH = (n + 1023) / 1024;  // 49
    __shared__ int wsum[32];
    int t = threadIdx.x, lane = t & 31, w = t >> 5;
    int c0 = t * CH;
    int local = 0;
    for (int i = 0; i < CH; i++) {
        int idx = c0 + i;
        if (idx < n) local += g_deg[idx];
    }
    int v = local;
#pragma unroll
    for (int o = 1; o < 32; o <<= 1) {
        int u = __shfl_up_sync(0xffffffffu, v, o);
        if (lane >= o) v += u;
    }
    if (lane == 31) wsum[w] = v;
    __syncthreads();
    if (w == 0) {
        int x = wsum[lane];
#pragma unroll
        for (int o = 1; o < 32; o <<= 1) {
            int u = __shfl_up_sync(0xffffffffu, x, o);
            if (lane >= o) x += u;
        }
        wsum[lane] = x;
    }
    __syncthreads();
    int excl = (v - local) + (w > 0 ? wsum[w - 1] : 0);
    int run = excl;
    for (int i = 0; i < CH; i++) {
        int idx = c0 + i;
        if (idx < n) {
            int d = g_deg[idx];
            g_rowptr[idx] = run;
            run += d;
            g_invdeg[idx] = 1.0f / fmaxf((float)d, 1.0f);
        }
    }
    if (t == 1023) g_rowptr[n] = wsum[31];
}

__global__ void k_scatter(const int* __restrict__ src, const int* __restrict__ dst) {
    int e = blockIdx.x * blockDim.x + threadIdx.x;
    if (e < EE) {
        int d = dst[e];
        int pos = g_rowptr[d] + atomicAdd(&g_fill[d], 1);
        g_csr[pos] = src[e];
    }
}

// ================= BF16 tensor-core GEMM (cp.async + ldmatrix + double buffer) =================
// SMALL=false: C[N,512] = A @ W[512,256]^T, split outputs stride 256.
// SMALL=true : C[N,128] = A @ W2[128,256]^T; cols 0-39 -> Cs (stride 64), 40-79 -> Cn, rest dropped.
#define PLW 1536  // words per plane (128*12)

template <bool SMALL>
__global__ void __launch_bounds__(256, 2) k_gemm_pre(
    const uint32_t* __restrict__ Ahi, const uint32_t* __restrict__ Alo,
    const uint32_t* __restrict__ Whi, const uint32_t* __restrict__ Wlo,
    int N, float* __restrict__ Cs, float* __restrict__ Cn) {
    __shared__ __align__(16) uint32_t sm[2][4][PLW];

    const int tid = threadIdx.x;
    const int lane = tid & 31;
    const int wid = tid >> 5;
    const int wm = (wid >> 2) * 64;
    const int wn = (wid & 3) * 32;
    const int g = lane >> 2;
    const int t = lane & 3;
    const int bm = blockIdx.y * 128;
    const int bn = blockIdx.x * 128;

    const int lr = tid >> 1;           // 0..127
    const int lh = (tid & 1) * 4;      // word offset 0 or 4
    const int arow = bm + lr;
    const bool aok = arow < N;
    const uint32_t* gA_h = Ahi + (size_t)(aok ? arow : 0) * 128 + lh;
    const uint32_t* gA_l = Alo + (size_t)(aok ? arow : 0) * 128 + lh;
    const uint32_t* gB_h = Whi + (size_t)(bn + lr) * 128 + lh;
    const uint32_t* gB_l = Wlo + (size_t)(bn + lr) * 128 + lh;
    const uint32_t asz = aok ? 16u : 0u;
    const int st_off = lr * 12 + lh;

    const uint32_t sbase = smem_u32(&sm[0][0][0]);
    const int a_row = wm + (lane & 15);
    const int a_word = (lane >> 4) << 2;
    const uint32_t aoff = (uint32_t)(a_row * 12 + a_word) * 4u;
    const int b_row = wn + ((lane >> 4) << 3) + (lane & 7);
    const int b_word = ((lane >> 3) & 1) << 2;
    const uint32_t boff = (uint32_t)(b_row * 12 + b_word) * 4u;

    float acc[4][4][4];
#pragma unroll
    for (int i = 0; i < 4; i++)
#pragma unroll
        for (int j = 0; j < 4; j++)
#pragma unroll
            for (int r = 0; r < 4; r++) acc[i][j][r] = 0.0f;

    auto issue_chunk = [&](int c, int buf) {
        uint32_t bo = sbase + (uint32_t)buf * (4u * PLW * 4u);
        cp_async16(bo + (uint32_t)(0 * PLW + st_off) * 4u, gA_h + c * 8, asz);
        cp_async16(bo + (uint32_t)(1 * PLW + st_off) * 4u, gA_l + c * 8, asz);
        cp_async16(bo + (uint32_t)(2 * PLW + st_off) * 4u, gB_h + c * 8, 16u);
        cp_async16(bo + (uint32_t)(3 * PLW + st_off) * 4u, gB_l + c * 8, 16u);
        cp_commit();
    };

    issue_chunk(0, 0);
    cp_wait0();
    __syncthreads();

    for (int kc = 0; kc < 16; kc++) {
        const int buf = kc & 1;
        if (kc < 15) issue_chunk(kc + 1, buf ^ 1);

        const uint32_t bufb = sbase + (uint32_t)buf * (4u * PLW * 4u);
        uint32_t ah[4][4], al[4][4];
#pragma unroll
        for (int mt = 0; mt < 4; mt++) {
            ldsm4(ah[mt], bufb + 0 * (PLW * 4) + aoff + mt * 768);
            ldsm4(al[mt], bufb + 1 * (PLW * 4) + aoff + mt * 768);
        }
#pragma unroll
        for (int p = 0; p < 2; p++) {
            uint32_t bh[4], bl[4];
            ldsm4(bh, bufb + 2 * (PLW * 4) + boff + p * 768);
            ldsm4(bl, bufb + 3 * (PLW * 4) + boff + p * 768);
#pragma unroll
            for (int s = 0; s < 2; s++) {
                const int nt = p * 2 + s;
#pragma unroll
                for (int mt = 0; mt < 4; mt++) {
                    mma_bf16(acc[mt][nt], ah[mt], &bh[s * 2]);  // hi*hi
                    mma_bf16(acc[mt][nt], ah[mt], &bl[s * 2]);  // hi*lo
                    mma_bf16(acc[mt][nt], al[mt], &bh[s * 2]);  // lo*hi
                }
            }
        }
        cp_wait0();
        __syncthreads();
    }

    if (!SMALL) {
        float* Cbase = (bn < 256) ? (Cs + bn) : (Cn + (bn - 256));
#pragma unroll
        for (int mt = 0; mt < 4; mt++) {
#pragma unroll
            for (int nt = 0; nt < 4; nt++) {
                int row = bm + wm + mt * 16 + g;
                int col = wn + nt * 8 + 2 * t;
                if (row < N)
                    *reinterpret_cast<float2*>(Cbase + (size_t)row * 256 + col) =
                        make_float2(acc[mt][nt][0], acc[mt][nt][1]);
                if (row + 8 < N)
                    *reinterpret_cast<float2*>(Cbase + (size_t)(row + 8) * 256 + col) =
                        make_float2(acc[mt][nt][2], acc[mt][nt][3]);
            }
        }
    } else {
#pragma unroll
        for (int mt = 0; mt < 4; mt++) {
#pragma unroll
            for (int nt = 0; nt < 4; nt++) {
                int row = bm + wm + mt * 16 + g;
                int col = wn + nt * 8 + 2 * t;
                float* dst;
                if (col < NCLS) dst = Cs + (size_t)row * 64 + col;
                else if (col < 2 * NCLS) dst = Cn + (size_t)row * 64 + (col - NCLS);
                else continue;
                if (row < N)
                    *reinterpret_cast<float2*>(dst) =
                        make_float2(acc[mt][nt][0], acc[mt][nt][1]);
                if (row + 8 < N)
                    *reinterpret_cast<float2*>(dst + 8 * 64) =
                        make_float2(acc[mt][nt][2], acc[mt][nt][3]);
            }
        }
    }
}

// ---------------- Aggregation (float4, 4 nodes per block, 8-deep MLP) ----------------
__global__ void __launch_bounds__(256) k_agg4(
    const float* __restrict__ Gs, const float* __restrict__ Gn,
    const float* __restrict__ bias, float* __restrict__ Z) {
    int sub = threadIdx.x >> 6;
    int cg = (threadIdx.x & 63) << 2;
    int i = blockIdx.x * 4 + sub;
    int e0 = g_rowptr[i];
    int e1 = g_rowptr[i + 1];
    float4 acc = make_float4(0.f, 0.f, 0.f, 0.f);
    int e = e0;
    for (; e + 8 <= e1; e += 8) {
        int s[8];
#pragma unroll
        for (int j = 0; j < 8; j++) s[j] = g_csr[e + j];
        float4 v[8];
#pragma unroll
        for (int j = 0; j < 8; j++)
            v[j] = __ldg(reinterpret_cast<const float4*>(Gn + (size_t)s[j] * DD + cg));
        float4 p0, p1, p2, p3;
        p0.x = v[0].x + v[1].x; p0.y = v[0].y + v[1].y; p0.z = v[0].z + v[1].z; p0.w = v[0].w + v[1].w;
        p1.x = v[2].x + v[3].x; p1.y = v[2].y + v[3].y; p1.z = v[2].z + v[3].z; p1.w = v[2].w + v[3].w;
        p2.x = v[4].x + v[5].x; p2.y = v[4].y + v[5].y; p2.z = v[4].z + v[5].z; p2.w = v[4].w + v[5].w;
        p3.x = v[6].x + v[7].x; p3.y = v[6].y + v[7].y; p3.z = v[6].z + v[7].z; p3.w = v[6].w + v[7].w;
        acc.x += (p0.x + p1.x) + (p2.x + p3.x);
        acc.y += (p0.y + p1.y) + (p2.y + p3.y);
        acc.z += (p0.z + p1.z) + (p2.z + p3.z);
        acc.w += (p0.w + p1.w) + (p2.w + p3.w);
    }
    for (; e + 2 <= e1; e += 2) {
        int s0 = g_csr[e], s1 = g_csr[e + 1];
        float4 v0 = __ldg(reinterpret_cast<const float4*>(Gn + (size_t)s0 * DD + cg));
        float4 v1 = __ldg(reinterpret_cast<const float4*>(Gn + (size_t)s1 * DD + cg));
        acc.x += v0.x + v1.x; acc.y += v0.y + v1.y;
        acc.z += v0.z + v1.z; acc.w += v0.w + v1.w;
    }
    if (e < e1) {
        float4 v = __ldg(reinterpret_cast<const float4*>(Gn + (size_t)g_csr[e] * DD + cg));
        acc.x += v.x; acc.y += v.y; acc.z += v.z; acc.w += v.w;
    }
    float inv = g_invdeg[i];
    float4 self = *reinterpret_cast<const float4*>(Gs + (size_t)i * DD + cg);
    float4 b = *reinterpret_cast<const float4*>(bias + cg);
    float4 r;
    r.x = fmaf(inv, acc.x, self.x) + b.x;
    r.y = fmaf(inv, acc.y, self.y) + b.y;
    r.z = fmaf(inv, acc.z, self.z) + b.z;
    r.w = fmaf(inv, acc.w, self.w) + b.w;
    *reinterpret_cast<float4*>(Z + (size_t)i * DD + cg) = r;
}

// scalar agg for layer 2 (D = NCLS = 40), Gs/Gn rows padded to stride 64 (256B aligned)
__global__ void k_agg_small(const float* __restrict__ Gs, const float* __restrict__ Gn,
                            const float* __restrict__ bias, float* __restrict__ Z) {
    int i = blockIdx.x;
    int c = threadIdx.x;
    if (c >= NCLS) return;
    int e0 = g_rowptr[i];
    int e1 = g_rowptr[i + 1];
    float accn = 0.0f;
    int e = e0;
    for (; e + 4 <= e1; e += 4) {
        int s0 = g_csr[e + 0];
        int s1 = g_csr[e + 1];
        int s2 = g_csr[e + 2];
        int s3 = g_csr[e + 3];
        float v0 = __ldg(Gn + (size_t)s0 * 64 + c);
        float v1 = __ldg(Gn + (size_t)s1 * 64 + c);
        float v2 = __ldg(Gn + (size_t)s2 * 64 + c);
        float v3 = __ldg(Gn + (size_t)s3 * 64 + c);
        accn += (v0 + v1) + (v2 + v3);
    }
    for (; e < e1; e++) accn += __ldg(Gn + (size_t)g_csr[e] * 64 + c);
    Z[i * NCLS + c] = fmaf(g_invdeg[i], accn, Gs[(size_t)i * 64 + c]) + bias[c];
}

// ---------------- column stats (deterministic 2-stage) ----------------
__global__ void k_colstats(const float* __restrict__ X) {
    int c = threadIdx.x;
    int rows_per = (NN + gridDim.x - 1) / gridDim.x;
    int r0 = blockIdx.x * rows_per;
    int r1 = min(NN, r0 + rows_per);
    float s = 0.f, s2 = 0.f;
#pragma unroll 4
    for (int r = r0; r < r1; r++) {
        float v = X[r * DD + c];
        s += v;
        s2 = fmaf(v, v, s2);
    }
    g_part[blockIdx.x * 512 + c] = s;
    g_part[blockIdx.x * 512 + 256 + c] = s2;
}

__global__ void k_affine(const float* __restrict__ gamma, const float* __restrict__ beta,
                         float* __restrict__ AB) {
    int c = threadIdx.x;
    float s = 0.f, s2 = 0.f;
    for (int b = 0; b < STATS_BLOCKS; b++) {
        s += g_part[b * 512 + c];
        s2 += g_part[b * 512 + 256 + c];
    }
    float m = s / (float)NN;
    float var = s2 / (float)NN - m * m;
    float a = gamma[c] * rsqrtf(var + BN_EPS);
    AB[c] = a;
    AB[256 + c] = beta[c] - m * a;
}

// ---------------- launch ----------------
extern "C" void kernel_launch(void* const* d_in, const int* in_sizes, int n_in,
                              void* d_out, int out_size) {
    const float* LLM = (const float*)d_in[0];
    const float* PLM = (const float*)d_in[1];
    const int* src   = (const int*)d_in[2];
    const int* dst   = (const int*)d_in[3];
    const float* ws0 = (const float*)d_in[4];
    const float* wn0 = (const float*)d_in[5];
    const float* b0  = (const float*)d_in[6];
    const float* ws1 = (const float*)d_in[7];
    const float* wn1 = (const float*)d_in[8];
    const float* b1  = (const float*)d_in[9];
    const float* ws2 = (const float*)d_in[10];
    const float* wn2 = (const float*)d_in[11];
    const float* b2  = (const float*)d_in[12];
    const float* bn0w = (const float*)d_in[13];
    const float* bn0b = (const float*)d_in[14];
    const float* bn1w = (const float*)d_in[15];
    const float* bn1b = (const float*)d_in[16];
    float* out = (float*)d_out;

    float *pGs, *pGn, *pZ, *pAff;
    uint32_t *pAhi, *pAlo, *pWhi, *pWlo, *pW1hi, *pW1lo, *pW2hi, *pW2lo;
    cudaGetSymbolAddress((void**)&pGs, g_Gs);
    cudaGetSymbolAddress((void**)&pGn, g_Gn);
    cudaGetSymbolAddress((void**)&pZ, g_Z);
    cudaGetSymbolAddress((void**)&pAff, g_affine);
    cudaGetSymbolAddress((void**)&pAhi, g_Ahi);
    cudaGetSymbolAddress((void**)&pAlo, g_Alo);
    cudaGetSymbolAddress((void**)&pWhi, g_Whi);
    cudaGetSymbolAddress((void**)&pWlo, g_Wlo);
    cudaGetSymbolAddress((void**)&pW1hi, g_W1hi);
    cudaGetSymbolAddress((void**)&pW1lo, g_W1lo);
    cudaGetSymbolAddress((void**)&pW2hi, g_W2hi);
    cudaGetSymbolAddress((void**)&pW2lo, g_W2lo);

    // side stream + fork/join events (created once; host resources)
    static cudaStream_t s2 = nullptr;
    static cudaEvent_t evF = nullptr, evJ = nullptr;
    if (s2 == nullptr) {
        cudaStreamCreateWithFlags(&s2, cudaStreamNonBlocking);
        cudaEventCreateWithFlags(&evF, cudaEventDisableTiming);
        cudaEventCreateWithFlags(&evJ, cudaEventDisableTiming);
    }

    dim3 ggemm(4, (NN + 127) / 128);
    dim3 ggemm2(1, (NN + 127) / 128);
    const int splita_blocks = NN * 64 / 256;   // 12500, exact
    const int splitw_blocks = 512 * 64 / 256;  // 128
    const int splitw2_blocks = 128 * 64 / 256; // 32

    // ---- fork: later-layer weight splits + CSR build + PLM stats on side stream ----
    cudaEventRecord(evF, 0);
    cudaStreamWaitEvent(s2, evF, 0);
    k_split_w<<<splitw_blocks, 256, 0, s2>>>(ws1, wn1, pW1hi, pW1lo);
    k_split_w2<<<splitw2_blocks, 256, 0, s2>>>(ws2, wn2, pW2hi, pW2lo);
    k_zero<<<(NN / 4 + 255) / 256, 256, 0, s2>>>();
    k_hist<<<(EE + 255) / 256, 256, 0, s2>>>(dst);
    k_scan<<<1, 1024, 0, s2>>>();
    k_scatter<<<(EE + 255) / 256, 256, 0, s2>>>(src, dst);
    k_colstats<<<STATS_BLOCKS, 256, 0, s2>>>(PLM);
    k_affine<<<1, 256, 0, s2>>>(bn0w, bn0b, pAff + 512);
    cudaEventRecord(evJ, s2);

    // ---- main stream: layer-0 split + GEMM ----
    k_split_w<<<splitw_blocks, 256>>>(ws0, wn0, pWhi, pWlo);
    k_split_a<0><<<splita_blocks, 256>>>(LLM, nullptr, nullptr, pAhi, pAlo);
    k_gemm_pre<false><<<ggemm, 256>>>(pAhi, pAlo, pWhi, pWlo, NN, pGs, pGn);

    // ---- join ----
    cudaStreamWaitEvent(0, evJ, 0);

    // layer 0 aggregate -> Z0, bn0 affine
    k_agg4<<<NN / 4, 256>>>(pGs, pGn, b0, pZ);
    k_colstats<<<STATS_BLOCKS, 256>>>(pZ);
    k_affine<<<1, 256>>>(bn0w, bn0b, pAff);

    // layer 1: fused bn0+residual+relu in split, GEMM, aggregate
    k_split_a<1><<<splita_blocks, 256>>>(pZ, PLM, pAff, pAhi, pAlo);
    k_gemm_pre<false><<<ggemm, 256>>>(pAhi, pAlo, pW1hi, pW1lo, NN, pGs, pGn);
    k_agg4<<<NN / 4, 256>>>(pGs, pGn, b1, pZ);

    // bn1 affine
    k_colstats<<<STATS_BLOCKS, 256>>>(pZ);
    k_affine<<<1, 256>>>(bn1w, bn1b, pAff);

    // layer 2: fused bn1+relu in split, tensor GEMM (padded), aggregate -> out
    k_split_a<2><<<splita_blocks, 256>>>(pZ, nullptr, pAff, pAhi, pAlo);
    k_gemm_pre<true><<<ggemm2, 256>>>(pAhi, pAlo, pW2hi, pW2lo, NN, pGs, pGn);
    k_agg_small<<<NN, 64>>>(pGs, pGn, b2, out);

    (void)in_sizes; (void)n_in; (void)out_size;
}

// round 12
// speedup vs baseline: 1.1709x; 1.1709x over previous
#include <cuda_runtime.h>
#include <cstdint>

// Problem constants (fixed shapes)
#define NN 50000
#define EE 800000
#define DD 256
#define KK 256
#define NCLS 40
#define STATS_BLOCKS 400
#define BN_EPS 1e-5f

// ---------------- scratch (static device globals; no allocation) ----------------
__device__ __align__(16) float g_Gs[NN * DD];     // GEMM self output [N,256]
__device__ __align__(16) float g_Gn[NN * DD];     // GEMM neigh output [N,256]
__device__ __align__(16) float g_Z[NN * DD];      // pre-BN activations
__device__ __align__(16) uint32_t g_Ahi[NN * 128];   // A hi-plane (bf16x2 words)
__device__ __align__(16) uint32_t g_Alo[NN * 128];   // A lo-plane
__device__ __align__(16) uint32_t g_Whi[512 * 128];  // W hi-plane [self;neigh]
__device__ __align__(16) uint32_t g_Wlo[512 * 128];  // W lo-plane
__device__ __align__(16) uint32_t g_W2hi[128 * 128]; // W2 planes (40 self + 40 neigh + pad)
__device__ __align__(16) uint32_t g_W2lo[128 * 128];
__device__ float g_part[STATS_BLOCKS * 512];
__device__ float g_affine[1024];  // [0:256)=A_z,[256:512)=B_z,[512:768)=A_plm,[768:1024)=B_plm
__device__ float g_invdeg[NN];
__device__ __align__(16) int g_deg[NN];
__device__ __align__(16) int g_fill[NN];
__device__ int g_rowptr[NN + 1];
__device__ int g_csr[EE];

// ---------------- bf16 hi/lo split helpers ----------------
__device__ __forceinline__ uint32_t pack_bf16x2(float lo_elem, float hi_elem) {
    uint32_t r;
    asm("cvt.rn.bf16x2.f32 %0, %1, %2;" : "=r"(r) : "f"(hi_elem), "f"(lo_elem));
    return r;
}

__device__ __forceinline__ void split_pair(float v0, float v1, uint32_t& hi, uint32_t& lo) {
    uint32_t h = pack_bf16x2(v0, v1);
    float h0 = __uint_as_float(h << 16);
    float h1 = __uint_as_float(h & 0xffff0000u);
    lo = pack_bf16x2(v0 - h0, v1 - h1);
    hi = h;
}

__device__ __forceinline__ void split4(float4 v, uint2& h, uint2& l) {
    uint32_t h0, l0, h1, l1;
    split_pair(v.x, v.y, h0, l0);
    split_pair(v.z, v.w, h1, l1);
    h = make_uint2(h0, h1);
    l = make_uint2(l0, l1);
}

__device__ __forceinline__ void mma_bf16(float* d, const uint32_t* a, const uint32_t* b) {
    asm volatile(
        "mma.sync.aligned.m16n8k16.row.col.f32.bf16.bf16.f32 "
        "{%0,%1,%2,%3}, {%4,%5,%6,%7}, {%8,%9}, {%0,%1,%2,%3};"
        : "+f"(d[0]), "+f"(d[1]), "+f"(d[2]), "+f"(d[3])
        : "r"(a[0]), "r"(a[1]), "r"(a[2]), "r"(a[3]), "r"(b[0]), "r"(b[1]));
}

__device__ __forceinline__ void ldsm4(uint32_t* r, uint32_t addr) {
    asm volatile("ldmatrix.sync.aligned.m8n8.x4.shared.b16 {%0,%1,%2,%3}, [%4];"
                 : "=r"(r[0]), "=r"(r[1]), "=r"(r[2]), "=r"(r[3])
                 : "r"(addr));
}

__device__ __forceinline__ uint32_t smem_u32(const void* p) {
    uint32_t a;
    asm("{ .reg .u64 t; cvta.to.shared.u64 t, %1; cvt.u32.u64 %0, t; }" : "=r"(a) : "l"(p));
    return a;
}

__device__ __forceinline__ void cp_async16(uint32_t dst, const void* src, uint32_t sz) {
    asm volatile("cp.async.cg.shared.global [%0], [%1], 16, %2;"
                 :: "r"(dst), "l"(src), "r"(sz) : "memory");
}
__device__ __forceinline__ void cp_commit() {
    asm volatile("cp.async.commit_group;" ::: "memory");
}
__device__ __forceinline__ void cp_wait0() {
    asm volatile("cp.async.wait_group 0;" ::: "memory");
}

// ---------------- split kernels ----------------
__global__ void k_split_w(const float* __restrict__ Bs, const float* __restrict__ Bn,
                          uint32_t* __restrict__ Whi, uint32_t* __restrict__ Wlo) {
    int q = blockIdx.x * blockDim.x + threadIdx.x;  // float4 idx, 512*64
    int row = q >> 6, wq = q & 63;
    const float* src = (row < 256) ? (Bs + row * KK) : (Bn + (row - 256) * KK);
    float4 v = *reinterpret_cast<const float4*>(src + wq * 4);
    uint2 h, l;
    split4(v, h, l);
    *reinterpret_cast<uint2*>(Whi + row * 128 + wq * 2) = h;
    *reinterpret_cast<uint2*>(Wlo + row * 128 + wq * 2) = l;
}

// layer-2 weights: rows 0-39 = ws2, 40-79 = wn2, 80-127 = zero pad
__global__ void k_split_w2(const float* __restrict__ Bs, const float* __restrict__ Bn,
                           uint32_t* __restrict__ Whi, uint32_t* __restrict__ Wlo) {
    int q = blockIdx.x * blockDim.x + threadIdx.x;  // float4 idx, 128*64 = 8192
    int row = q >> 6, wq = q & 63;
    float4 v = make_float4(0.f, 0.f, 0.f, 0.f);
    if (row < NCLS) v = *reinterpret_cast<const float4*>(Bs + row * KK + wq * 4);
    else if (row < 2 * NCLS) v = *reinterpret_cast<const float4*>(Bn + (row - NCLS) * KK + wq * 4);
    uint2 h, l;
    split4(v, h, l);
    *reinterpret_cast<uint2*>(Whi + row * 128 + wq * 2) = h;
    *reinterpret_cast<uint2*>(Wlo + row * 128 + wq * 2) = l;
}

// Activations: MODE 0 = raw copy-split; MODE 1 = relu(Az*A+Bz + Ap*P+Bp) then split
template <int MODE>
__global__ void k_split_a(const float* __restrict__ A, const float* __restrict__ P,
                          const float* __restrict__ aff,
                          uint32_t* __restrict__ Ahi, uint32_t* __restrict__ Alo) {
    int q = blockIdx.x * blockDim.x + threadIdx.x;  // float4 idx, NN*64 exact
    float4 a = reinterpret_cast<const float4*>(A)[q];
    if (MODE == 1) {
        int cb = (q & 63) << 2;
        float4 az = *reinterpret_cast<const float4*>(aff + cb);
        float4 bz = *reinterpret_cast<const float4*>(aff + 256 + cb);
        float4 ap = *reinterpret_cast<const float4*>(aff + 512 + cb);
        float4 bp = *reinterpret_cast<const float4*>(aff + 768 + cb);
        float4 p = reinterpret_cast<const float4*>(P)[q];
        a.x = fmaxf(fmaf(az.x, a.x, bz.x) + fmaf(ap.x, p.x, bp.x), 0.f);
        a.y = fmaxf(fmaf(az.y, a.y, bz.y) + fmaf(ap.y, p.y, bp.y), 0.f);
        a.z = fmaxf(fmaf(az.z, a.z, bz.z) + fmaf(ap.z, p.z, bp.z), 0.f);
        a.w = fmaxf(fmaf(az.w, a.w, bz.w) + fmaf(ap.w, p.w, bp.w), 0.f);
    }
    uint2 h, l;
    split4(a, h, l);
    reinterpret_cast<uint2*>(Ahi)[q] = h;
    reinterpret_cast<uint2*>(Alo)[q] = l;
}

// ---------------- zero deg/fill ----------------
__global__ void k_zero() {
    int q = blockIdx.x * blockDim.x + threadIdx.x;
    if (q < NN / 4) {
        int4 z = make_int4(0, 0, 0, 0);
        reinterpret_cast<int4*>(g_deg)[q] = z;
        reinterpret_cast<int4*>(g_fill)[q] = z;
    }
}

// ---------------- CSR build ----------------
__global__ void k_hist(const int* __restrict__ dst) {
    int e = blockIdx.x * blockDim.x + threadIdx.x;
    if (e < EE) atomicAdd(&g_deg[dst[e]], 1);
}

__global__ void k_scan() {
    const int n = NN;
    const int CH = (n + 1023) / 1024;  // 49
    __shared__ int wsum[32];
    int t = threadIdx.x, lane = t & 31, w = t >> 5;
    int c0 = t * CH;
    int local = 0;
    for (int i = 0; i < CH; i++) {
        int idx = c0 + i;
        if (idx < n) local += g_deg[idx];
    }
    int v = local;
#pragma unroll
    for (int o = 1; o < 32; o <<= 1) {
        int u = __shfl_up_sync(0xffffffffu, v, o);
        if (lane >= o) v += u;
    }
    if (lane == 31) wsum[w] = v;
    __syncthreads();
    if (w == 0) {
        int x = wsum[lane];
#pragma unroll
        for (int o = 1; o < 32; o <<= 1) {
            int u = __shfl_up_sync(0xffffffffu, x, o);
            if (lane >= o) x += u;
        }
        wsum[lane] = x;
    }
    __syncthreads();
    int excl = (v - local) + (w > 0 ? wsum[w - 1] : 0);
    int run = excl;
    for (int i = 0; i < CH; i++) {
        int idx = c0 + i;
        if (idx < n) {
            int d = g_deg[idx];
            g_rowptr[idx] = run;
            run += d;
            g_invdeg[idx] = 1.0f / fmaxf((float)d, 1.0f);
        }
    }
    if (t == 1023) g_rowptr[n] = wsum[31];
}

__global__ void k_scatter(const int* __restrict__ src, const int* __restrict__ dst) {
    int e = blockIdx.x * blockDim.x + threadIdx.x;
    if (e < EE) {
        int d = dst[e];
        int pos = g_rowptr[d] + atomicAdd(&g_fill[d], 1);
        g_csr[pos] = src[e];
    }
}

// ================= BF16 tensor-core GEMM (cp.async + ldmatrix + double buffer) =================
// C[N,512] = A[N,256] @ W[512,256]^T, 3-term hi/lo accumulation, split outputs.
#define PLW 1536  // words per plane (128*12)

__global__ void __launch_bounds__(256, 2) k_gemm_pre(
    const uint32_t* __restrict__ Ahi, const uint32_t* __restrict__ Alo,
    const uint32_t* __restrict__ Whi, const uint32_t* __restrict__ Wlo,
    int N, float* __restrict__ Cs, float* __restrict__ Cn) {
    __shared__ __align__(16) uint32_t sm[2][4][PLW];

    const int tid = threadIdx.x;
    const int lane = tid & 31;
    const int wid = tid >> 5;
    const int wm = (wid >> 2) * 64;
    const int wn = (wid & 3) * 32;
    const int g = lane >> 2;
    const int t = lane & 3;
    const int bm = blockIdx.y * 128;
    const int bn = blockIdx.x * 128;

    const int lr = tid >> 1;           // 0..127
    const int lh = (tid & 1) * 4;      // word offset 0 or 4
    const int arow = bm + lr;
    const bool aok = arow < N;
    const uint32_t* gA_h = Ahi + (size_t)(aok ? arow : 0) * 128 + lh;
    const uint32_t* gA_l = Alo + (size_t)(aok ? arow : 0) * 128 + lh;
    const uint32_t* gB_h = Whi + (size_t)(bn + lr) * 128 + lh;
    const uint32_t* gB_l = Wlo + (size_t)(bn + lr) * 128 + lh;
    const uint32_t asz = aok ? 16u : 0u;
    const int st_off = lr * 12 + lh;

    const uint32_t sbase = smem_u32(&sm[0][0][0]);
    const int a_row = wm + (lane & 15);
    const int a_word = (lane >> 4) << 2;
    const uint32_t aoff = (uint32_t)(a_row * 12 + a_word) * 4u;
    const int b_row = wn + ((lane >> 4) << 3) + (lane & 7);
    const int b_word = ((lane >> 3) & 1) << 2;
    const uint32_t boff = (uint32_t)(b_row * 12 + b_word) * 4u;

    float acc[4][4][4];
#pragma unroll
    for (int i = 0; i < 4; i++)
#pragma unroll
        for (int j = 0; j < 4; j++)
#pragma unroll
            for (int r = 0; r < 4; r++) acc[i][j][r] = 0.0f;

    auto issue_chunk = [&](int c, int buf) {
        uint32_t bo = sbase + (uint32_t)buf * (4u * PLW * 4u);
        cp_async16(bo + (uint32_t)(0 * PLW + st_off) * 4u, gA_h + c * 8, asz);
        cp_async16(bo + (uint32_t)(1 * PLW + st_off) * 4u, gA_l + c * 8, asz);
        cp_async16(bo + (uint32_t)(2 * PLW + st_off) * 4u, gB_h + c * 8, 16u);
        cp_async16(bo + (uint32_t)(3 * PLW + st_off) * 4u, gB_l + c * 8, 16u);
        cp_commit();
    };

    issue_chunk(0, 0);
    cp_wait0();
    __syncthreads();

    for (int kc = 0; kc < 16; kc++) {
        const int buf = kc & 1;
        if (kc < 15) issue_chunk(kc + 1, buf ^ 1);

        const uint32_t bufb = sbase + (uint32_t)buf * (4u * PLW * 4u);
        uint32_t ah[4][4], al[4][4];
#pragma unroll
        for (int mt = 0; mt < 4; mt++) {
            ldsm4(ah[mt], bufb + 0 * (PLW * 4) + aoff + mt * 768);
            ldsm4(al[mt], bufb + 1 * (PLW * 4) + aoff + mt * 768);
        }
#pragma unroll
        for (int p = 0; p < 2; p++) {
            uint32_t bh[4], bl[4];
            ldsm4(bh, bufb + 2 * (PLW * 4) + boff + p * 768);
            ldsm4(bl, bufb + 3 * (PLW * 4) + boff + p * 768);
#pragma unroll
            for (int s = 0; s < 2; s++) {
                const int nt = p * 2 + s;
#pragma unroll
                for (int mt = 0; mt < 4; mt++) {
                    mma_bf16(acc[mt][nt], ah[mt], &bh[s * 2]);  // hi*hi
                    mma_bf16(acc[mt][nt], ah[mt], &bl[s * 2]);  // hi*lo
                    mma_bf16(acc[mt][nt], al[mt], &bh[s * 2]);  // lo*hi
                }
            }
        }
        cp_wait0();
        __syncthreads();
    }

    float* Cbase = (bn < 256) ? (Cs + bn) : (Cn + (bn - 256));
#pragma unroll
    for (int mt = 0; mt < 4; mt++) {
#pragma unroll
        for (int nt = 0; nt < 4; nt++) {
            int row = bm + wm + mt * 16 + g;
            int col = wn + nt * 8 + 2 * t;
            if (row < N)
                *reinterpret_cast<float2*>(Cbase + (size_t)row * 256 + col) =
                    make_float2(acc[mt][nt][0], acc[mt][nt][1]);
            if (row + 8 < N)
                *reinterpret_cast<float2*>(Cbase + (size_t)(row + 8) * 256 + col) =
                    make_float2(acc[mt][nt][2], acc[mt][nt][3]);
        }
    }
}

// ========== small tensor GEMM: C[N,80] = relu(bn1(Z)) @ W2[80,256]^T ==========
// Inline bn1+relu+hi/lo split on the A loader (each element converted once;
// grid (1,391)). B from padded 128-row W2 planes via cp.async. Compact stride-40 output.
__global__ void __launch_bounds__(256, 2) k_gemm_small_tc(
    const float* __restrict__ Z, const float* __restrict__ aff,
    const uint32_t* __restrict__ Whi, const uint32_t* __restrict__ Wlo,
    int N, float* __restrict__ Cs, float* __restrict__ Cn) {
    __shared__ __align__(16) uint32_t sm[2][4][PLW];

    const int tid = threadIdx.x;
    const int lane = tid & 31;
    const int wid = tid >> 5;
    const int wm = (wid >> 2) * 64;
    const int wn = (wid & 3) * 32;
    const int g = lane >> 2;
    const int t = lane & 3;
    const int bm = blockIdx.y * 128;

    const int lr = tid >> 1;           // 0..127
    const int lh = (tid & 1) * 4;      // word offset 0 or 4 (floats: 8*(tid&1))
    const int fo = (tid & 1) * 8;      // float col offset within chunk
    const int arow = bm + lr;
    const bool aok = arow < N;
    const float* gZ = Z + (size_t)(aok ? arow : 0) * 256 + fo;
    const uint32_t* gB_h = Whi + (size_t)lr * 128 + lh;
    const uint32_t* gB_l = Wlo + (size_t)lr * 128 + lh;
    const int st_off = lr * 12 + lh;

    const uint32_t sbase = smem_u32(&sm[0][0][0]);
    const int a_row = wm + (lane & 15);
    const int a_word = (lane >> 4) << 2;
    const uint32_t aoff = (uint32_t)(a_row * 12 + a_word) * 4u;
    const int b_row = wn + ((lane >> 4) << 3) + (lane & 7);
    const int b_word = ((lane >> 3) & 1) << 2;
    const uint32_t boff = (uint32_t)(b_row * 12 + b_word) * 4u;

    float acc[4][4][4];
#pragma unroll
    for (int i = 0; i < 4; i++)
#pragma unroll
        for (int j = 0; j < 4; j++)
#pragma unroll
            for (int r = 0; r < 4; r++) acc[i][j][r] = 0.0f;

    auto issue_b = [&](int c, int buf) {
        uint32_t bo = sbase + (uint32_t)buf * (4u * PLW * 4u);
        cp_async16(bo + (uint32_t)(2 * PLW + st_off) * 4u, gB_h + c * 8, 16u);
        cp_async16(bo + (uint32_t)(3 * PLW + st_off) * 4u, gB_l + c * 8, 16u);
        cp_commit();
    };

    // A chunk: load fp32, apply bn1+relu, split, store to buf planes
    auto load_a = [&](int c, float4& a0, float4& a1) {
        a0 = *reinterpret_cast<const float4*>(gZ + c * 16);
        a1 = *reinterpret_cast<const float4*>(gZ + c * 16 + 4);
    };
    auto store_a = [&](int c, int buf, float4 a0, float4 a1) {
        int cb = c * 16 + fo;
        float4 az0 = *reinterpret_cast<const float4*>(aff + cb);
        float4 bz0 = *reinterpret_cast<const float4*>(aff + 256 + cb);
        float4 az1 = *reinterpret_cast<const float4*>(aff + cb + 4);
        float4 bz1 = *reinterpret_cast<const float4*>(aff + 256 + cb + 4);
        float4 e0, e1;
        e0.x = fmaxf(fmaf(az0.x, a0.x, bz0.x), 0.f);
        e0.y = fmaxf(fmaf(az0.y, a0.y, bz0.y), 0.f);
        e0.z = fmaxf(fmaf(az0.z, a0.z, bz0.z), 0.f);
        e0.w = fmaxf(fmaf(az0.w, a0.w, bz0.w), 0.f);
        e1.x = fmaxf(fmaf(az1.x, a1.x, bz1.x), 0.f);
        e1.y = fmaxf(fmaf(az1.y, a1.y, bz1.y), 0.f);
        e1.z = fmaxf(fmaf(az1.z, a1.z, bz1.z), 0.f);
        e1.w = fmaxf(fmaf(az1.w, a1.w, bz1.w), 0.f);
        uint2 h0, l0, h1, l1;
        split4(e0, h0, l0);
        split4(e1, h1, l1);
        uint32_t* bo = &sm[buf][0][0];
        *reinterpret_cast<uint4*>(bo + 0 * PLW + st_off) = make_uint4(h0.x, h0.y, h1.x, h1.y);
        *reinterpret_cast<uint4*>(bo + 1 * PLW + st_off) = make_uint4(l0.x, l0.y, l1.x, l1.y);
    };

    float4 pa0, pa1, na0, na1;
    load_a(0, pa0, pa1);
    store_a(0, 0, pa0, pa1);
    issue_b(0, 0);
    load_a(1, na0, na1);
    cp_wait0();
    __syncthreads();

    for (int kc = 0; kc < 16; kc++) {
        const int buf = kc & 1;
        if (kc < 15) {
            store_a(kc + 1, buf ^ 1, na0, na1);
            issue_b(kc + 1, buf ^ 1);
        }
        if (kc < 14) load_a(kc + 2, na0, na1);

        const uint32_t bufb = sbase + (uint32_t)buf * (4u * PLW * 4u);
        uint32_t ah[4][4], al[4][4];
#pragma unroll
        for (int mt = 0; mt < 4; mt++) {
            ldsm4(ah[mt], bufb + 0 * (PLW * 4) + aoff + mt * 768);
            ldsm4(al[mt], bufb + 1 * (PLW * 4) + aoff + mt * 768);
        }
#pragma unroll
        for (int p = 0; p < 2; p++) {
            uint32_t bh[4], bl[4];
            ldsm4(bh, bufb + 2 * (PLW * 4) + boff + p * 768);
            ldsm4(bl, bufb + 3 * (PLW * 4) + boff + p * 768);
#pragma unroll
            for (int s = 0; s < 2; s++) {
                const int nt = p * 2 + s;
#pragma unroll
                for (int mt = 0; mt < 4; mt++) {
                    mma_bf16(acc[mt][nt], ah[mt], &bh[s * 2]);
                    mma_bf16(acc[mt][nt], ah[mt], &bl[s * 2]);
                    mma_bf16(acc[mt][nt], al[mt], &bh[s * 2]);
                }
            }
        }
        cp_wait0();
        __syncthreads();
    }

    // epilogue: cols 0-39 -> Cs (stride 40), 40-79 -> Cn, 80-127 dropped
#pragma unroll
    for (int mt = 0; mt < 4; mt++) {
#pragma unroll
        for (int nt = 0; nt < 4; nt++) {
            int row = bm + wm + mt * 16 + g;
            int col = wn + nt * 8 + 2 * t;
            float* dst;
            if (col < NCLS) dst = Cs + (size_t)row * NCLS + col;
            else if (col < 2 * NCLS) dst = Cn + (size_t)row * NCLS + (col - NCLS);
            else continue;
            if (row < N)
                *reinterpret_cast<float2*>(dst) = make_float2(acc[mt][nt][0], acc[mt][nt][1]);
            if (row + 8 < N)
                *reinterpret_cast<float2*>(dst + 8 * NCLS) =
                    make_float2(acc[mt][nt][2], acc[mt][nt][3]);
        }
    }
}

// ---------------- Aggregation (float4, 4 nodes per block, 8-deep MLP) ----------------
__global__ void __launch_bounds__(256) k_agg4(
    const float* __restrict__ Gs, const float* __restrict__ Gn,
    const float* __restrict__ bias, float* __restrict__ Z) {
    int sub = threadIdx.x >> 6;
    int cg = (threadIdx.x & 63) << 2;
    int i = blockIdx.x * 4 + sub;
    int e0 = g_rowptr[i];
    int e1 = g_rowptr[i + 1];
    float4 acc = make_float4(0.f, 0.f, 0.f, 0.f);
    int e = e0;
    for (; e + 8 <= e1; e += 8) {
        int s[8];
#pragma unroll
        for (int j = 0; j < 8; j++) s[j] = g_csr[e + j];
        float4 v[8];
#pragma unroll
        for (int j = 0; j < 8; j++)
            v[j] = __ldg(reinterpret_cast<const float4*>(Gn + (size_t)s[j] * DD + cg));
        float4 p0, p1, p2, p3;
        p0.x = v[0].x + v[1].x; p0.y = v[0].y + v[1].y; p0.z = v[0].z + v[1].z; p0.w = v[0].w + v[1].w;
        p1.x = v[2].x + v[3].x; p1.y = v[2].y + v[3].y; p1.z = v[2].z + v[3].z; p1.w = v[2].w + v[3].w;
        p2.x = v[4].x + v[5].x; p2.y = v[4].y + v[5].y; p2.z = v[4].z + v[5].z; p2.w = v[4].w + v[5].w;
        p3.x = v[6].x + v[7].x; p3.y = v[6].y + v[7].y; p3.z = v[6].z + v[7].z; p3.w = v[6].w + v[7].w;
        acc.x += (p0.x + p1.x) + (p2.x + p3.x);
        acc.y += (p0.y + p1.y) + (p2.y + p3.y);
        acc.z += (p0.z + p1.z) + (p2.z + p3.z);
        acc.w += (p0.w + p1.w) + (p2.w + p3.w);
    }
    for (; e + 2 <= e1; e += 2) {
        int s0 = g_csr[e], s1 = g_csr[e + 1];
        float4 v0 = __ldg(reinterpret_cast<const float4*>(Gn + (size_t)s0 * DD + cg));
        float4 v1 = __ldg(reinterpret_cast<const float4*>(Gn + (size_t)s1 * DD + cg));
        acc.x += v0.x + v1.x; acc.y += v0.y + v1.y;
        acc.z += v0.z + v1.z; acc.w += v0.w + v1.w;
    }
    if (e < e1) {
        float4 v = __ldg(reinterpret_cast<const float4*>(Gn + (size_t)g_csr[e] * DD + cg));
        acc.x += v.x; acc.y += v.y; acc.z += v.z; acc.w += v.w;
    }
    float inv = g_invdeg[i];
    float4 self = *reinterpret_cast<const float4*>(Gs + (size_t)i * DD + cg);
    float4 b = *reinterpret_cast<const float4*>(bias + cg);
    float4 r;
    r.x = fmaf(inv, acc.x, self.x) + b.x;
    r.y = fmaf(inv, acc.y, self.y) + b.y;
    r.z = fmaf(inv, acc.z, self.z) + b.z;
    r.w = fmaf(inv, acc.w, self.w) + b.w;
    *reinterpret_cast<float4*>(Z + (size_t)i * DD + cg) = r;
}

// scalar agg for layer 2 (D = NCLS = 40)
__global__ void k_agg_small(const float* __restrict__ Gs, const float* __restrict__ Gn,
                            const float* __restrict__ bias, float* __restrict__ Z) {
    int i = blockIdx.x;
    int c = threadIdx.x;
    if (c >= NCLS) return;
    int e0 = g_rowptr[i];
    int e1 = g_rowptr[i + 1];
    float accn = 0.0f;
    int e = e0;
    for (; e + 4 <= e1; e += 4) {
        int s0 = g_csr[e + 0];
        int s1 = g_csr[e + 1];
        int s2 = g_csr[e + 2];
        int s3 = g_csr[e + 3];
        float v0 = __ldg(Gn + s0 * NCLS + c);
        float v1 = __ldg(Gn + s1 * NCLS + c);
        float v2 = __ldg(Gn + s2 * NCLS + c);
        float v3 = __ldg(Gn + s3 * NCLS + c);
        accn += (v0 + v1) + (v2 + v3);
    }
    for (; e < e1; e++) accn += __ldg(Gn + g_csr[e] * NCLS + c);
    Z[i * NCLS + c] = fmaf(g_invdeg[i], accn, Gs[i * NCLS + c]) + bias[c];
}

// ---------------- column stats (deterministic 2-stage) ----------------
__global__ void k_colstats(const float* __restrict__ X) {
    int c = threadIdx.x;
    int rows_per = (NN + gridDim.x - 1) / gridDim.x;
    int r0 = blockIdx.x * rows_per;
    int r1 = min(NN, r0 + rows_per);
    float s = 0.f, s2 = 0.f;
#pragma unroll 4
    for (int r = r0; r < r1; r++) {
        float v = X[r * DD + c];
        s += v;
        s2 = fmaf(v, v, s2);
    }
    g_part[blockIdx.x * 512 + c] = s;
    g_part[blockIdx.x * 512 + 256 + c] = s2;
}

__global__ void k_affine(const float* __restrict__ gamma, const float* __restrict__ beta,
                         float* __restrict__ AB) {
    int c = threadIdx.x;
    float s = 0.f, s2 = 0.f;
    for (int b = 0; b < STATS_BLOCKS; b++) {
        s += g_part[b * 512 + c];
        s2 += g_part[b * 512 + 256 + c];
    }
    float m = s / (float)NN;
    float var = s2 / (float)NN - m * m;
    float a = gamma[c] * rsqrtf(var + BN_EPS);
    AB[c] = a;
    AB[256 + c] = beta[c] - m * a;
}

// ---------------- launch ----------------
extern "C" void kernel_launch(void* const* d_in, const int* in_sizes, int n_in,
                              void* d_out, int out_size) {
    const float* LLM = (const float*)d_in[0];
    const float* PLM = (const float*)d_in[1];
    const int* src   = (const int*)d_in[2];
    const int* dst   = (const int*)d_in[3];
    const float* ws0 = (const float*)d_in[4];
    const float* wn0 = (const float*)d_in[5];
    const float* b0  = (const float*)d_in[6];
    const float* ws1 = (const float*)d_in[7];
    const float* wn1 = (const float*)d_in[8];
    const float* b1  = (const float*)d_in[9];
    const float* ws2 = (const float*)d_in[10];
    const float* wn2 = (const float*)d_in[11];
    const float* b2  = (const float*)d_in[12];
    const float* bn0w = (const float*)d_in[13];
    const float* bn0b = (const float*)d_in[14];
    const float* bn1w = (const float*)d_in[15];
    const float* bn1b = (const float*)d_in[16];
    float* out = (float*)d_out;

    float *pGs, *pGn, *pZ, *pAff;
    uint32_t *pAhi, *pAlo, *pWhi, *pWlo, *pW2hi, *pW2lo;
    cudaGetSymbolAddress((void**)&pGs, g_Gs);
    cudaGetSymbolAddress((void**)&pGn, g_Gn);
    cudaGetSymbolAddress((void**)&pZ, g_Z);
    cudaGetSymbolAddress((void**)&pAff, g_affine);
    cudaGetSymbolAddress((void**)&pAhi, g_Ahi);
    cudaGetSymbolAddress((void**)&pAlo, g_Alo);
    cudaGetSymbolAddress((void**)&pWhi, g_Whi);
    cudaGetSymbolAddress((void**)&pWlo, g_Wlo);
    cudaGetSymbolAddress((void**)&pW2hi, g_W2hi);
    cudaGetSymbolAddress((void**)&pW2lo, g_W2lo);

    // side stream + fork/join events (created once; host resources)
    static cudaStream_t s2 = nullptr;
    static cudaEvent_t evF = nullptr, evJ = nullptr;
    if (s2 == nullptr) {
        cudaStreamCreateWithFlags(&s2, cudaStreamNonBlocking);
        cudaEventCreateWithFlags(&evF, cudaEventDisableTiming);
        cudaEventCreateWithFlags(&evJ, cudaEventDisableTiming);
    }

    dim3 ggemm(4, (NN + 127) / 128);
    dim3 ggemm2(1, (NN + 127) / 128);
    const int splita_blocks = NN * 64 / 256;   // 12500, exact
    const int splitw_blocks = 512 * 64 / 256;  // 128
    const int splitw2_blocks = 128 * 64 / 256; // 32

    // ---- fork: CSR build + PLM stats + W2 split on side stream ----
    cudaEventRecord(evF, 0);
    cudaStreamWaitEvent(s2, evF, 0);
    k_zero<<<(NN / 4 + 255) / 256, 256, 0, s2>>>();
    k_hist<<<(EE + 255) / 256, 256, 0, s2>>>(dst);
    k_scan<<<1, 1024, 0, s2>>>();
    k_scatter<<<(EE + 255) / 256, 256, 0, s2>>>(src, dst);
    k_colstats<<<STATS_BLOCKS, 256, 0, s2>>>(PLM);
    k_affine<<<1, 256, 0, s2>>>(bn0w, bn0b, pAff + 512);
    k_split_w2<<<splitw2_blocks, 256, 0, s2>>>(ws2, wn2, pW2hi, pW2lo);
    cudaEventRecord(evJ, s2);

    // ---- main stream: layer-0 split + GEMM ----
    k_split_w<<<splitw_blocks, 256>>>(ws0, wn0, pWhi, pWlo);
    k_split_a<0><<<splita_blocks, 256>>>(LLM, nullptr, nullptr, pAhi, pAlo);
    k_gemm_pre<<<ggemm, 256>>>(pAhi, pAlo, pWhi, pWlo, NN, pGs, pGn);

    // ---- join ----
    cudaStreamWaitEvent(0, evJ, 0);

    // layer 0 aggregate -> Z0, bn0 affine
    k_agg4<<<NN / 4, 256>>>(pGs, pGn, b0, pZ);
    k_colstats<<<STATS_BLOCKS, 256>>>(pZ);
    k_affine<<<1, 256>>>(bn0w, bn0b, pAff);

    // layer 1: fused bn0+residual+relu inside split, then GEMM + aggregate
    k_split_a<1><<<splita_blocks, 256>>>(pZ, PLM, pAff, pAhi, pAlo);
    k_split_w<<<splitw_blocks, 256>>>(ws1, wn1, pWhi, pWlo);
    k_gemm_pre<<<ggemm, 256>>>(pAhi, pAlo, pWhi, pWlo, NN, pGs, pGn);
    k_agg4<<<NN / 4, 256>>>(pGs, pGn, b1, pZ);

    // bn1 affine
    k_colstats<<<STATS_BLOCKS, 256>>>(pZ);
    k_affine<<<1, 256>>>(bn1w, bn1b, pAff);

    // layer 2: tensor GEMM with inline bn1+relu+split, aggregate -> out
    k_gemm_small_tc<<<ggemm2, 256>>>(pZ, pAff, pW2hi, pW2lo, NN, pGs, pGn);
    k_agg_small<<<NN, 64>>>(pGs, pGn, b2, out);

    (void)in_sizes; (void)n_in; (void)out_size;
}

// round 13
// speedup vs baseline: 1.1870x; 1.0137x over previous
#include <cuda_runtime.h>
#include <cstdint>

// Problem constants (fixed shapes)
#define NN 50000
#define EE 800000
#define DD 256
#define KK 256
#define NCLS 40
#define STATS_BLOCKS 400
#define BN_EPS 1e-5f

// ---------------- scratch (static device globals; no allocation) ----------------
__device__ __align__(16) float g_Gs[NN * DD];     // GEMM self output [N,256]
__device__ __align__(16) float g_Gn[NN * DD];     // GEMM neigh output [N,256]
__device__ __align__(16) float g_Z[NN * DD];      // pre-BN activations
__device__ __align__(16) uint32_t g_Ahi[NN * 128];   // A hi-plane (bf16x2 words)
__device__ __align__(16) uint32_t g_Alo[NN * 128];   // A lo-plane
__device__ __align__(16) uint32_t g_Whi[512 * 128];  // W0 hi-plane [self;neigh]
__device__ __align__(16) uint32_t g_Wlo[512 * 128];  // W0 lo-plane
__device__ __align__(16) uint32_t g_W1hi[512 * 128]; // W1 planes
__device__ __align__(16) uint32_t g_W1lo[512 * 128];
__device__ __align__(16) uint32_t g_W2hi[128 * 128]; // W2 planes (40 self + 40 neigh + pad)
__device__ __align__(16) uint32_t g_W2lo[128 * 128];
__device__ float g_part[STATS_BLOCKS * 512];
__device__ float g_affine[1024];  // [0:256)=A_z,[256:512)=B_z,[512:768)=A_plm,[768:1024)=B_plm
__device__ float g_invdeg[NN];
__device__ __align__(16) int g_deg[NN];
__device__ __align__(16) int g_fill[NN];
__device__ int g_rowptr[NN + 1];
__device__ int g_csr[EE];

// ---------------- bf16 hi/lo split helpers ----------------
__device__ __forceinline__ uint32_t pack_bf16x2(float lo_elem, float hi_elem) {
    uint32_t r;
    asm("cvt.rn.bf16x2.f32 %0, %1, %2;" : "=r"(r) : "f"(hi_elem), "f"(lo_elem));
    return r;
}

__device__ __forceinline__ void split_pair(float v0, float v1, uint32_t& hi, uint32_t& lo) {
    uint32_t h = pack_bf16x2(v0, v1);
    float h0 = __uint_as_float(h << 16);
    float h1 = __uint_as_float(h & 0xffff0000u);
    lo = pack_bf16x2(v0 - h0, v1 - h1);
    hi = h;
}

__device__ __forceinline__ void split4(float4 v, uint2& h, uint2& l) {
    uint32_t h0, l0, h1, l1;
    split_pair(v.x, v.y, h0, l0);
    split_pair(v.z, v.w, h1, l1);
    h = make_uint2(h0, h1);
    l = make_uint2(l0, l1);
}

__device__ __forceinline__ void mma_bf16(float* d, const uint32_t* a, const uint32_t* b) {
    asm volatile(
        "mma.sync.aligned.m16n8k16.row.col.f32.bf16.bf16.f32 "
        "{%0,%1,%2,%3}, {%4,%5,%6,%7}, {%8,%9}, {%0,%1,%2,%3};"
        : "+f"(d[0]), "+f"(d[1]), "+f"(d[2]), "+f"(d[3])
        : "r"(a[0]), "r"(a[1]), "r"(a[2]), "r"(a[3]), "r"(b[0]), "r"(b[1]));
}

__device__ __forceinline__ void ldsm4(uint32_t* r, uint32_t addr) {
    asm volatile("ldmatrix.sync.aligned.m8n8.x4.shared.b16 {%0,%1,%2,%3}, [%4];"
                 : "=r"(r[0]), "=r"(r[1]), "=r"(r[2]), "=r"(r[3])
                 : "r"(addr));
}

__device__ __forceinline__ uint32_t smem_u32(const void* p) {
    uint32_t a;
    asm("{ .reg .u64 t; cvta.to.shared.u64 t, %1; cvt.u32.u64 %0, t; }" : "=r"(a) : "l"(p));
    return a;
}

__device__ __forceinline__ void cp_async16(uint32_t dst, const void* src, uint32_t sz) {
    asm volatile("cp.async.cg.shared.global [%0], [%1], 16, %2;"
                 :: "r"(dst), "l"(src), "r"(sz) : "memory");
}
__device__ __forceinline__ void cp_commit() {
    asm volatile("cp.async.commit_group;" ::: "memory");
}
__device__ __forceinline__ void cp_wait0() {
    asm volatile("cp.async.wait_group 0;" ::: "memory");
}
__device__ __forceinline__ void cp_wait1() {
    asm volatile("cp.async.wait_group 1;" ::: "memory");
}

// ---------------- split kernels ----------------
__global__ void k_split_w(const float* __restrict__ Bs, const float* __restrict__ Bn,
                          uint32_t* __restrict__ Whi, uint32_t* __restrict__ Wlo) {
    int q = blockIdx.x * blockDim.x + threadIdx.x;  // float4 idx, 512*64
    int row = q >> 6, wq = q & 63;
    const float* src = (row < 256) ? (Bs + row * KK) : (Bn + (row - 256) * KK);
    float4 v = *reinterpret_cast<const float4*>(src + wq * 4);
    uint2 h, l;
    split4(v, h, l);
    *reinterpret_cast<uint2*>(Whi + row * 128 + wq * 2) = h;
    *reinterpret_cast<uint2*>(Wlo + row * 128 + wq * 2) = l;
}

// layer-2 weights: rows 0-39 = ws2, 40-79 = wn2, 80-127 = zero pad
__global__ void k_split_w2(const float* __restrict__ Bs, const float* __restrict__ Bn,
                           uint32_t* __restrict__ Whi, uint32_t* __restrict__ Wlo) {
    int q = blockIdx.x * blockDim.x + threadIdx.x;  // float4 idx, 128*64 = 8192
    int row = q >> 6, wq = q & 63;
    float4 v = make_float4(0.f, 0.f, 0.f, 0.f);
    if (row < NCLS) v = *reinterpret_cast<const float4*>(Bs + row * KK + wq * 4);
    else if (row < 2 * NCLS) v = *reinterpret_cast<const float4*>(Bn + (row - NCLS) * KK + wq * 4);
    uint2 h, l;
    split4(v, h, l);
    *reinterpret_cast<uint2*>(Whi + row * 128 + wq * 2) = h;
    *reinterpret_cast<uint2*>(Wlo + row * 128 + wq * 2) = l;
}

// Activations: MODE 0 = raw copy-split; MODE 1 = relu(Az*A+Bz + Ap*P+Bp) then split
template <int MODE>
__global__ void k_split_a(const float* __restrict__ A, const float* __restrict__ P,
                          const float* __restrict__ aff,
                          uint32_t* __restrict__ Ahi, uint32_t* __restrict__ Alo) {
    int q = blockIdx.x * blockDim.x + threadIdx.x;  // float4 idx, NN*64 exact
    float4 a = reinterpret_cast<const float4*>(A)[q];
    if (MODE == 1) {
        int cb = (q & 63) << 2;
        float4 az = *reinterpret_cast<const float4*>(aff + cb);
        float4 bz = *reinterpret_cast<const float4*>(aff + 256 + cb);
        float4 ap = *reinterpret_cast<const float4*>(aff + 512 + cb);
        float4 bp = *reinterpret_cast<const float4*>(aff + 768 + cb);
        float4 p = reinterpret_cast<const float4*>(P)[q];
        a.x = fmaxf(fmaf(az.x, a.x, bz.x) + fmaf(ap.x, p.x, bp.x), 0.f);
        a.y = fmaxf(fmaf(az.y, a.y, bz.y) + fmaf(ap.y, p.y, bp.y), 0.f);
        a.z = fmaxf(fmaf(az.z, a.z, bz.z) + fmaf(ap.z, p.z, bp.z), 0.f);
        a.w = fmaxf(fmaf(az.w, a.w, bz.w) + fmaf(ap.w, p.w, bp.w), 0.f);
    }
    uint2 h, l;
    split4(a, h, l);
    reinterpret_cast<uint2*>(Ahi)[q] = h;
    reinterpret_cast<uint2*>(Alo)[q] = l;
}

// ---------------- zero deg/fill ----------------
__global__ void k_zero() {
    int q = blockIdx.x * blockDim.x + threadIdx.x;
    if (q < NN / 4) {
        int4 z = make_int4(0, 0, 0, 0);
        reinterpret_cast<int4*>(g_deg)[q] = z;
        reinterpret_cast<int4*>(g_fill)[q] = z;
    }
}

// ---------------- CSR build ----------------
__global__ void k_hist(const int* __restrict__ dst) {
    int e = blockIdx.x * blockDim.x + threadIdx.x;
    if (e < EE) atomicAdd(&g_deg[dst[e]], 1);
}

__global__ void k_scan() {
    const int n = NN;
    const int CH = (n + 1023) / 1024;  // 49
    __shared__ int wsum[32];
    int t = threadIdx.x, lane = t & 31, w = t >> 5;
    int c0 = t * CH;
    int local = 0;
    for (int i = 0; i < CH; i++) {
        int idx = c0 + i;
        if (idx < n) local += g_deg[idx];
    }
    int v = local;
#pragma unroll
    for (int o = 1; o < 32; o <<= 1) {
        int u = __shfl_up_sync(0xffffffffu, v, o);
        if (lane >= o) v += u;
    }
    if (lane == 31) wsum[w] = v;
    __syncthreads();
    if (w == 0) {
        int x = wsum[lane];
#pragma unroll
        for (int o = 1; o < 32; o <<= 1) {
            int u = __shfl_up_sync(0xffffffffu, x, o);
            if (lane >= o) x += u;
        }
        wsum[lane] = x;
    }
    __syncthreads();
    int excl = (v - local) + (w > 0 ? wsum[w - 1] : 0);
    int run = excl;
    for (int i = 0; i < CH; i++) {
        int idx = c0 + i;
        if (idx < n) {
            int d = g_deg[idx];
            g_rowptr[idx] = run;
            run += d;
            g_invdeg[idx] = 1.0f / fmaxf((float)d, 1.0f);
        }
    }
    if (t == 1023) g_rowptr[n] = wsum[31];
}

__global__ void k_scatter(const int* __restrict__ src, const int* __restrict__ dst) {
    int e = blockIdx.x * blockDim.x + threadIdx.x;
    if (e < EE) {
        int d = dst[e];
        int pos = g_rowptr[d] + atomicAdd(&g_fill[d], 1);
        g_csr[pos] = src[e];
    }
}

// ================= BF16 tensor-core GEMM (3-stage cp.async + ldmatrix) =================
// C[N,512] = A[N,256] @ W[512,256]^T, 3-term hi/lo accumulation, split outputs.
#define PLW 1536  // words per plane (128*12)
#define GEMM_SMEM (3 * 4 * PLW * 4)  // 72 KB dynamic

__global__ void __launch_bounds__(256, 2) k_gemm_pre(
    const uint32_t* __restrict__ Ahi, const uint32_t* __restrict__ Alo,
    const uint32_t* __restrict__ Whi, const uint32_t* __restrict__ Wlo,
    int N, float* __restrict__ Cs, float* __restrict__ Cn) {
    extern __shared__ uint32_t smd[];

    const int tid = threadIdx.x;
    const int lane = tid & 31;
    const int wid = tid >> 5;
    const int wm = (wid >> 2) * 64;
    const int wn = (wid & 3) * 32;
    const int g = lane >> 2;
    const int t = lane & 3;
    const int bm = blockIdx.y * 128;
    const int bn = blockIdx.x * 128;

    const int lr = tid >> 1;           // 0..127
    const int lh = (tid & 1) * 4;      // word offset 0 or 4
    const int arow = bm + lr;
    const bool aok = arow < N;
    const uint32_t* gA_h = Ahi + (size_t)(aok ? arow : 0) * 128 + lh;
    const uint32_t* gA_l = Alo + (size_t)(aok ? arow : 0) * 128 + lh;
    const uint32_t* gB_h = Whi + (size_t)(bn + lr) * 128 + lh;
    const uint32_t* gB_l = Wlo + (size_t)(bn + lr) * 128 + lh;
    const uint32_t asz = aok ? 16u : 0u;
    const int st_off = lr * 12 + lh;

    const uint32_t sbase = smem_u32(smd);
    const int a_row = wm + (lane & 15);
    const int a_word = (lane >> 4) << 2;
    const uint32_t aoff = (uint32_t)(a_row * 12 + a_word) * 4u;
    const int b_row = wn + ((lane >> 4) << 3) + (lane & 7);
    const int b_word = ((lane >> 3) & 1) << 2;
    const uint32_t boff = (uint32_t)(b_row * 12 + b_word) * 4u;

    float acc[4][4][4];
#pragma unroll
    for (int i = 0; i < 4; i++)
#pragma unroll
        for (int j = 0; j < 4; j++)
#pragma unroll
            for (int r = 0; r < 4; r++) acc[i][j][r] = 0.0f;

    auto issue_chunk = [&](int c, int buf) {
        uint32_t bo = sbase + (uint32_t)buf * (4u * PLW * 4u);
        cp_async16(bo + (uint32_t)(0 * PLW + st_off) * 4u, gA_h + c * 8, asz);
        cp_async16(bo + (uint32_t)(1 * PLW + st_off) * 4u, gA_l + c * 8, asz);
        cp_async16(bo + (uint32_t)(2 * PLW + st_off) * 4u, gB_h + c * 8, 16u);
        cp_async16(bo + (uint32_t)(3 * PLW + st_off) * 4u, gB_l + c * 8, 16u);
        cp_commit();
    };

    issue_chunk(0, 0);
    issue_chunk(1, 1);

    for (int kc = 0; kc < 16; kc++) {
        const int buf = kc % 3;
        cp_wait1();       // chunk kc has landed (chunk kc+1 may still be in flight)
        __syncthreads();  // also guarantees prior iteration's LDSMs on this buf are done
        if (kc + 2 < 16) issue_chunk(kc + 2, (kc + 2) % 3);

        const uint32_t bufb = sbase + (uint32_t)buf * (4u * PLW * 4u);
        uint32_t ah[4][4], al[4][4];
#pragma unroll
        for (int mt = 0; mt < 4; mt++) {
            ldsm4(ah[mt], bufb + 0 * (PLW * 4) + aoff + mt * 768);
            ldsm4(al[mt], bufb + 1 * (PLW * 4) + aoff + mt * 768);
        }
#pragma unroll
        for (int p = 0; p < 2; p++) {
            uint32_t bh[4], bl[4];
            ldsm4(bh, bufb + 2 * (PLW * 4) + boff + p * 768);
            ldsm4(bl, bufb + 3 * (PLW * 4) + boff + p * 768);
#pragma unroll
            for (int s = 0; s < 2; s++) {
                const int nt = p * 2 + s;
#pragma unroll
                for (int mt = 0; mt < 4; mt++) {
                    mma_bf16(acc[mt][nt], ah[mt], &bh[s * 2]);  // hi*hi
                    mma_bf16(acc[mt][nt], ah[mt], &bl[s * 2]);  // hi*lo
                    mma_bf16(acc[mt][nt], al[mt], &bh[s * 2]);  // lo*hi
                }
            }
        }
    }

    float* Cbase = (bn < 256) ? (Cs + bn) : (Cn + (bn - 256));
#pragma unroll
    for (int mt = 0; mt < 4; mt++) {
#pragma unroll
        for (int nt = 0; nt < 4; nt++) {
            int row = bm + wm + mt * 16 + g;
            int col = wn + nt * 8 + 2 * t;
            if (row < N)
                *reinterpret_cast<float2*>(Cbase + (size_t)row * 256 + col) =
                    make_float2(acc[mt][nt][0], acc[mt][nt][1]);
            if (row + 8 < N)
                *reinterpret_cast<float2*>(Cbase + (size_t)(row + 8) * 256 + col) =
                    make_float2(acc[mt][nt][2], acc[mt][nt][3]);
        }
    }
}

// ========== small tensor GEMM: C[N,80] = relu(bn1(Z)) @ W2[80,256]^T ==========
// Inline bn1+relu+hi/lo split on the A loader; compact stride-40 output. (2-stage, static smem)
__global__ void __launch_bounds__(256, 2) k_gemm_small_tc(
    const float* __restrict__ Z, const float* __restrict__ aff,
    const uint32_t* __restrict__ Whi, const uint32_t* __restrict__ Wlo,
    int N, float* __restrict__ Cs, float* __restrict__ Cn) {
    __shared__ __align__(16) uint32_t sm[2][4][PLW];

    const int tid = threadIdx.x;
    const int lane = tid & 31;
    const int wid = tid >> 5;
    const int wm = (wid >> 2) * 64;
    const int wn = (wid & 3) * 32;
    const int g = lane >> 2;
    const int t = lane & 3;
    const int bm = blockIdx.y * 128;

    const int lr = tid >> 1;
    const int lh = (tid & 1) * 4;
    const int fo = (tid & 1) * 8;
    const int arow = bm + lr;
    const bool aok = arow < N;
    const float* gZ = Z + (size_t)(aok ? arow : 0) * 256 + fo;
    const uint32_t* gB_h = Whi + (size_t)lr * 128 + lh;
    const uint32_t* gB_l = Wlo + (size_t)lr * 128 + lh;
    const int st_off = lr * 12 + lh;

    const uint32_t sbase = smem_u32(&sm[0][0][0]);
    const int a_row = wm + (lane & 15);
    const int a_word = (lane >> 4) << 2;
    const uint32_t aoff = (uint32_t)(a_row * 12 + a_word) * 4u;
    const int b_row = wn + ((lane >> 4) << 3) + (lane & 7);
    const int b_word = ((lane >> 3) & 1) << 2;
    const uint32_t boff = (uint32_t)(b_row * 12 + b_word) * 4u;

    float acc[4][4][4];
#pragma unroll
    for (int i = 0; i < 4; i++)
#pragma unroll
        for (int j = 0; j < 4; j++)
#pragma unroll
            for (int r = 0; r < 4; r++) acc[i][j][r] = 0.0f;

    auto issue_b = [&](int c, int buf) {
        uint32_t bo = sbase + (uint32_t)buf * (4u * PLW * 4u);
        cp_async16(bo + (uint32_t)(2 * PLW + st_off) * 4u, gB_h + c * 8, 16u);
        cp_async16(bo + (uint32_t)(3 * PLW + st_off) * 4u, gB_l + c * 8, 16u);
        cp_commit();
    };

    auto load_a = [&](int c, float4& a0, float4& a1) {
        a0 = *reinterpret_cast<const float4*>(gZ + c * 16);
        a1 = *reinterpret_cast<const float4*>(gZ + c * 16 + 4);
    };
    auto store_a = [&](int c, int buf, float4 a0, float4 a1) {
        int cb = c * 16 + fo;
        float4 az0 = *reinterpret_cast<const float4*>(aff + cb);
        float4 bz0 = *reinterpret_cast<const float4*>(aff + 256 + cb);
        float4 az1 = *reinterpret_cast<const float4*>(aff + cb + 4);
        float4 bz1 = *reinterpret_cast<const float4*>(aff + 256 + cb + 4);
        float4 e0, e1;
        e0.x = fmaxf(fmaf(az0.x, a0.x, bz0.x), 0.f);
        e0.y = fmaxf(fmaf(az0.y, a0.y, bz0.y), 0.f);
        e0.z = fmaxf(fmaf(az0.z, a0.z, bz0.z), 0.f);
        e0.w = fmaxf(fmaf(az0.w, a0.w, bz0.w), 0.f);
        e1.x = fmaxf(fmaf(az1.x, a1.x, bz1.x), 0.f);
        e1.y = fmaxf(fmaf(az1.y, a1.y, bz1.y), 0.f);
        e1.z = fmaxf(fmaf(az1.z, a1.z, bz1.z), 0.f);
        e1.w = fmaxf(fmaf(az1.w, a1.w, bz1.w), 0.f);
        uint2 h0, l0, h1, l1;
        split4(e0, h0, l0);
        split4(e1, h1, l1);
        uint32_t* bo = &sm[buf][0][0];
        *reinterpret_cast<uint4*>(bo + 0 * PLW + st_off) = make_uint4(h0.x, h0.y, h1.x, h1.y);
        *reinterpret_cast<uint4*>(bo + 1 * PLW + st_off) = make_uint4(l0.x, l0.y, l1.x, l1.y);
    };

    float4 pa0, pa1, na0, na1;
    load_a(0, pa0, pa1);
    store_a(0, 0, pa0, pa1);
    issue_b(0, 0);
    load_a(1, na0, na1);
    cp_wait0();
    __syncthreads();

    for (int kc = 0; kc < 16; kc++) {
        const int buf = kc & 1;
        if (kc < 15) {
            store_a(kc + 1, buf ^ 1, na0, na1);
            issue_b(kc + 1, buf ^ 1);
        }
        if (kc < 14) load_a(kc + 2, na0, na1);

        const uint32_t bufb = sbase + (uint32_t)buf * (4u * PLW * 4u);
        uint32_t ah[4][4], al[4][4];
#pragma unroll
        for (int mt = 0; mt < 4; mt++) {
            ldsm4(ah[mt], bufb + 0 * (PLW * 4) + aoff + mt * 768);
            ldsm4(al[mt], bufb + 1 * (PLW * 4) + aoff + mt * 768);
        }
#pragma unroll
        for (int p = 0; p < 2; p++) {
            uint32_t bh[4], bl[4];
            ldsm4(bh, bufb + 2 * (PLW * 4) + boff + p * 768);
            ldsm4(bl, bufb + 3 * (PLW * 4) + boff + p * 768);
#pragma unroll
            for (int s = 0; s < 2; s++) {
                const int nt = p * 2 + s;
#pragma unroll
                for (int mt = 0; mt < 4; mt++) {
                    mma_bf16(acc[mt][nt], ah[mt], &bh[s * 2]);
                    mma_bf16(acc[mt][nt], ah[mt], &bl[s * 2]);
                    mma_bf16(acc[mt][nt], al[mt], &bh[s * 2]);
                }
            }
        }
        cp_wait0();
        __syncthreads();
    }

#pragma unroll
    for (int mt = 0; mt < 4; mt++) {
#pragma unroll
        for (int nt = 0; nt < 4; nt++) {
            int row = bm + wm + mt * 16 + g;
            int col = wn + nt * 8 + 2 * t;
            float* dst;
            if (col < NCLS) dst = Cs + (size_t)row * NCLS + col;
            else if (col < 2 * NCLS) dst = Cn + (size_t)row * NCLS + (col - NCLS);
            else continue;
            if (row < N)
                *reinterpret_cast<float2*>(dst) = make_float2(acc[mt][nt][0], acc[mt][nt][1]);
            if (row + 8 < N)
                *reinterpret_cast<float2*>(dst + 8 * NCLS) =
                    make_float2(acc[mt][nt][2], acc[mt][nt][3]);
        }
    }
}

// ---------------- Aggregation (float4, 4 nodes per block, 8-deep MLP) ----------------
__global__ void __launch_bounds__(256) k_agg4(
    const float* __restrict__ Gs, const float* __restrict__ Gn,
    const float* __restrict__ bias, float* __restrict__ Z) {
    int sub = threadIdx.x >> 6;
    int cg = (threadIdx.x & 63) << 2;
    int i = blockIdx.x * 4 + sub;
    int e0 = g_rowptr[i];
    int e1 = g_rowptr[i + 1];
    float4 acc = make_float4(0.f, 0.f, 0.f, 0.f);
    int e = e0;
    for (; e + 8 <= e1; e += 8) {
        int s[8];
#pragma unroll
        for (int j = 0; j < 8; j++) s[j] = g_csr[e + j];
        float4 v[8];
#pragma unroll
        for (int j = 0; j < 8; j++)
            v[j] = __ldg(reinterpret_cast<const float4*>(Gn + (size_t)s[j] * DD + cg));
        float4 p0, p1, p2, p3;
        p0.x = v[0].x + v[1].x; p0.y = v[0].y + v[1].y; p0.z = v[0].z + v[1].z; p0.w = v[0].w + v[1].w;
        p1.x = v[2].x + v[3].x; p1.y = v[2].y + v[3].y; p1.z = v[2].z + v[3].z; p1.w = v[2].w + v[3].w;
        p2.x = v[4].x + v[5].x; p2.y = v[4].y + v[5].y; p2.z = v[4].z + v[5].z; p2.w = v[4].w + v[5].w;
        p3.x = v[6].x + v[7].x; p3.y = v[6].y + v[7].y; p3.z = v[6].z + v[7].z; p3.w = v[6].w + v[7].w;
        acc.x += (p0.x + p1.x) + (p2.x + p3.x);
        acc.y += (p0.y + p1.y) + (p2.y + p3.y);
        acc.z += (p0.z + p1.z) + (p2.z + p3.z);
        acc.w += (p0.w + p1.w) + (p2.w + p3.w);
    }
    for (; e + 2 <= e1; e += 2) {
        int s0 = g_csr[e], s1 = g_csr[e + 1];
        float4 v0 = __ldg(reinterpret_cast<const float4*>(Gn + (size_t)s0 * DD + cg));
        float4 v1 = __ldg(reinterpret_cast<const float4*>(Gn + (size_t)s1 * DD + cg));
        acc.x += v0.x + v1.x; acc.y += v0.y + v1.y;
        acc.z += v0.z + v1.z; acc.w += v0.w + v1.w;
    }
    if (e < e1) {
        float4 v = __ldg(reinterpret_cast<const float4*>(Gn + (size_t)g_csr[e] * DD + cg));
        acc.x += v.x; acc.y += v.y; acc.z += v.z; acc.w += v.w;
    }
    float inv = g_invdeg[i];
    float4 self = *reinterpret_cast<const float4*>(Gs + (size_t)i * DD + cg);
    float4 b = *reinterpret_cast<const float4*>(bias + cg);
    float4 r;
    r.x = fmaf(inv, acc.x, self.x) + b.x;
    r.y = fmaf(inv, acc.y, self.y) + b.y;
    r.z = fmaf(inv, acc.z, self.z) + b.z;
    r.w = fmaf(inv, acc.w, self.w) + b.w;
    *reinterpret_cast<float4*>(Z + (size_t)i * DD + cg) = r;
}

// scalar agg for layer 2 (D = NCLS = 40)
__global__ void k_agg_small(const float* __restrict__ Gs, const float* __restrict__ Gn,
                            const float* __restrict__ bias, float* __restrict__ Z) {
    int i = blockIdx.x;
    int c = threadIdx.x;
    if (c >= NCLS) return;
    int e0 = g_rowptr[i];
    int e1 = g_rowptr[i + 1];
    float accn = 0.0f;
    int e = e0;
    for (; e + 4 <= e1; e += 4) {
        int s0 = g_csr[e + 0];
        int s1 = g_csr[e + 1];
        int s2 = g_csr[e + 2];
        int s3 = g_csr[e + 3];
        float v0 = __ldg(Gn + s0 * NCLS + c);
        float v1 = __ldg(Gn + s1 * NCLS + c);
        float v2 = __ldg(Gn + s2 * NCLS + c);
        float v3 = __ldg(Gn + s3 * NCLS + c);
        accn += (v0 + v1) + (v2 + v3);
    }
    for (; e < e1; e++) accn += __ldg(Gn + g_csr[e] * NCLS + c);
    Z[i * NCLS + c] = fmaf(g_invdeg[i], accn, Gs[i * NCLS + c]) + bias[c];
}

// ---------------- column stats (deterministic 2-stage) ----------------
__global__ void k_colstats(const float* __restrict__ X) {
    int c = threadIdx.x;
    int rows_per = (NN + gridDim.x - 1) / gridDim.x;
    int r0 = blockIdx.x * rows_per;
    int r1 = min(NN, r0 + rows_per);
    float s = 0.f, s2 = 0.f;
#pragma unroll 4
    for (int r = r0; r < r1; r++) {
        float v = X[r * DD + c];
        s += v;
        s2 = fmaf(v, v, s2);
    }
    g_part[blockIdx.x * 512 + c] = s;
    g_part[blockIdx.x * 512 + 256 + c] = s2;
}

__global__ void k_affine(const float* __restrict__ gamma, const float* __restrict__ beta,
                         float* __restrict__ AB) {
    int c = threadIdx.x;
    float s = 0.f, s2 = 0.f;
    for (int b = 0; b < STATS_BLOCKS; b++) {
        s += g_part[b * 512 + c];
        s2 += g_part[b * 512 + 256 + c];
    }
    float m = s / (float)NN;
    float var = s2 / (float)NN - m * m;
    float a = gamma[c] * rsqrtf(var + BN_EPS);
    AB[c] = a;
    AB[256 + c] = beta[c] - m * a;
}

// ---------------- launch ----------------
extern "C" void kernel_launch(void* const* d_in, const int* in_sizes, int n_in,
                              void* d_out, int out_size) {
    const float* LLM = (const float*)d_in[0];
    const float* PLM = (const float*)d_in[1];
    const int* src   = (const int*)d_in[2];
    const int* dst   = (const int*)d_in[3];
    const float* ws0 = (const float*)d_in[4];
    const float* wn0 = (const float*)d_in[5];
    const float* b0  = (const float*)d_in[6];
    const float* ws1 = (const float*)d_in[7];
    const float* wn1 = (const float*)d_in[8];
    const float* b1  = (const float*)d_in[9];
    const float* ws2 = (const float*)d_in[10];
    const float* wn2 = (const float*)d_in[11];
    const float* b2  = (const float*)d_in[12];
    const float* bn0w = (const float*)d_in[13];
    const float* bn0b = (const float*)d_in[14];
    const float* bn1w = (const float*)d_in[15];
    const float* bn1b = (const float*)d_in[16];
    float* out = (float*)d_out;

    float *pGs, *pGn, *pZ, *pAff;
    uint32_t *pAhi, *pAlo, *pWhi, *pWlo, *pW1hi, *pW1lo, *pW2hi, *pW2lo;
    cudaGetSymbolAddress((void**)&pGs, g_Gs);
    cudaGetSymbolAddress((void**)&pGn, g_Gn);
    cudaGetSymbolAddress((void**)&pZ, g_Z);
    cudaGetSymbolAddress((void**)&pAff, g_affine);
    cudaGetSymbolAddress((void**)&pAhi, g_Ahi);
    cudaGetSymbolAddress((void**)&pAlo, g_Alo);
    cudaGetSymbolAddress((void**)&pWhi, g_Whi);
    cudaGetSymbolAddress((void**)&pWlo, g_Wlo);
    cudaGetSymbolAddress((void**)&pW1hi, g_W1hi);
    cudaGetSymbolAddress((void**)&pW1lo, g_W1lo);
    cudaGetSymbolAddress((void**)&pW2hi, g_W2hi);
    cudaGetSymbolAddress((void**)&pW2lo, g_W2lo);

    // dynamic smem for 3-stage GEMM (idempotent; host-side attribute)
    cudaFuncSetAttribute(k_gemm_pre, cudaFuncAttributeMaxDynamicSharedMemorySize, GEMM_SMEM);

    // side stream + fork/join events (created once; host resources)
    static cudaStream_t s2 = nullptr;
    static cudaEvent_t evF = nullptr, evJ = nullptr;
    if (s2 == nullptr) {
        cudaStreamCreateWithFlags(&s2, cudaStreamNonBlocking);
        cudaEventCreateWithFlags(&evF, cudaEventDisableTiming);
        cudaEventCreateWithFlags(&evJ, cudaEventDisableTiming);
    }

    dim3 ggemm(4, (NN + 127) / 128);
    dim3 ggemm2(1, (NN + 127) / 128);
    const int splita_blocks = NN * 64 / 256;   // 12500, exact
    const int splitw_blocks = 512 * 64 / 256;  // 128
    const int splitw2_blocks = 128 * 64 / 256; // 32

    // ---- fork: CSR build + PLM stats + W1/W2 splits on side stream ----
    cudaEventRecord(evF, 0);
    cudaStreamWaitEvent(s2, evF, 0);
    k_zero<<<(NN / 4 + 255) / 256, 256, 0, s2>>>();
    k_hist<<<(EE + 255) / 256, 256, 0, s2>>>(dst);
    k_scan<<<1, 1024, 0, s2>>>();
    k_scatter<<<(EE + 255) / 256, 256, 0, s2>>>(src, dst);
    k_colstats<<<STATS_BLOCKS, 256, 0, s2>>>(PLM);
    k_affine<<<1, 256, 0, s2>>>(bn0w, bn0b, pAff + 512);
    k_split_w<<<splitw_blocks, 256, 0, s2>>>(ws1, wn1, pW1hi, pW1lo);
    k_split_w2<<<splitw2_blocks, 256, 0, s2>>>(ws2, wn2, pW2hi, pW2lo);
    cudaEventRecord(evJ, s2);

    // ---- main stream: layer-0 split + GEMM ----
    k_split_w<<<splitw_blocks, 256>>>(ws0, wn0, pWhi, pWlo);
    k_split_a<0><<<splita_blocks, 256>>>(LLM, nullptr, nullptr, pAhi, pAlo);
    k_gemm_pre<<<ggemm, 256, GEMM_SMEM>>>(pAhi, pAlo, pWhi, pWlo, NN, pGs, pGn);

    // ---- join ----
    cudaStreamWaitEvent(0, evJ, 0);

    // layer 0 aggregate -> Z0, bn0 affine
    k_agg4<<<NN / 4, 256>>>(pGs, pGn, b0, pZ);
    k_colstats<<<STATS_BLOCKS, 256>>>(pZ);
    k_affine<<<1, 256>>>(bn0w, bn0b, pAff);

    // layer 1: fused bn0+residual+relu inside split, then GEMM + aggregate
    k_split_a<1><<<splita_blocks, 256>>>(pZ, PLM, pAff, pAhi, pAlo);
    k_gemm_pre<<<ggemm, 256, GEMM_SMEM>>>(pAhi, pAlo, pW1hi, pW1lo, NN, pGs, pGn);
    k_agg4<<<NN / 4, 256>>>(pGs, pGn, b1, pZ);

    // bn1 affine
    k_colstats<<<STATS_BLOCKS, 256>>>(pZ);
    k_affine<<<1, 256>>>(bn1w, bn1b, pAff);

    // layer 2: tensor GEMM with inline bn1+relu+split, aggregate -> out
    k_gemm_small_tc<<<ggemm2, 256>>>(pZ, pAff, pW2hi, pW2lo, NN, pGs, pGn);
    k_agg_small<<<NN, 64>>>(pGs, pGn, b2, out);

    (void)in_sizes; (void)n_in; (void)out_size;
}